// round 11
// baseline (speedup 1.0000x reference)
#include <cuda_runtime.h>
#include <cuda_bf16.h>

#define LAT     32
#define HID     128
#define HSTR    132     // padded row stride (floats): 8 rsub rows -> banks {0,4,..,28}
#define GSZ     512     // 4*HID
#define NVAR    9
#define NSCEN   4
#define IH0_W   (NVAR + HID)   // 137
#define INIT_W  (LAT + HID)    // 160

#define M       32      // batch rows per CTA
#define THREADS 512
#define TM      4       // rows per thread (rows 8*r + rsub)
#define TJ      2       // hidden units per thread (one f32x2 pair)

typedef unsigned long long u64;

// -------- device scratch: weights relaid out [k][q][cg][4] --------
// per k-row (512 floats): q = gate-pair (0: gates0,1 ; 1: gates2,3)
//   float idx = k*512 + q*256 + cg*4 + g'*2 + jj   (g' = g&1)
__device__ __align__(16) float g_Wt0[HID * GSZ];        // W_hh0
__device__ __align__(16) float g_Wt1[2 * HID * GSZ];    // k<128: W_ih1, k>=128: W_hh1

__global__ void transpose_kernel(const float* __restrict__ W_hh0,
                                 const float* __restrict__ W_ih1,
                                 const float* __restrict__ W_hh1) {
    int i = blockIdx.x * blockDim.x + threadIdx.x;   // i = k*512 + col
    if (i >= HID * GSZ) return;
    int k = i >> 9, col = i & (GSZ - 1);
    int g = col >> 7, w = col & 127;
    int cg = w >> 1, jj = w & 1;
    int dst = (k << 9) + ((g >> 1) << 8) + (cg << 2) + ((g & 1) << 1) + jj;
    g_Wt0[dst]             = W_hh0[col * HID + k];
    g_Wt1[dst]             = W_ih1[col * HID + k];
    g_Wt1[HID * GSZ + dst] = W_hh1[col * HID + k];
}

__device__ __forceinline__ float sigf(float x) {
    return __fdividef(1.0f, 1.0f + __expf(-x));
}
__device__ __forceinline__ float tanh_fast(float x) {
    return __fdividef(2.0f, 1.0f + __expf(-2.0f * x)) - 1.0f;
}

// ---- packed fp32x2 helpers (sm_103a FFMA2 path) ----
__device__ __forceinline__ u64 pack2(float lo, float hi) {
    u64 d;
    asm("mov.b64 %0, {%1, %2};" : "=l"(d) : "f"(lo), "f"(hi));
    return d;
}
__device__ __forceinline__ void unpack2(u64 v, float& lo, float& hi) {
    asm("mov.b64 {%0, %1}, %2;" : "=f"(lo), "=f"(hi) : "l"(v));
}
__device__ __forceinline__ u64 ffma2(u64 a, u64 b, u64 c) {
    u64 d;
    asm("fma.rn.f32x2 %0, %1, %2, %3;" : "=l"(d) : "l"(a), "l"(b), "l"(c));
    return d;
}

// acc[g][r] (+)= shH[8r+rsub][k] * W[k][col-pair cg], K = 128, packed pairs.
// CTA's 16 warps cover 64 disjoint cgs -> each weight byte read once per CTA.
__device__ __forceinline__ void gemm128_2(u64 acc[4][TM],
                                          const float* __restrict__ Wt,
                                          const float* __restrict__ shH,
                                          int rsub, int cg) {
    const float* wbase = Wt + (cg << 2);
    const float* hbase = shH + rsub * HSTR;
    for (int k = 0; k < HID; k += 4) {
        float4 h[TM];
#pragma unroll
        for (int r = 0; r < TM; ++r)
            h[r] = *(const float4*)(hbase + r * (8 * HSTR) + k);
#pragma unroll
        for (int kh = 0; kh < 4; kh += 2) {
            const float* w0p = wbase + ((k + kh) << 9);
            const float* w1p = wbase + ((k + kh + 1) << 9);
            longlong2 a0 = *(const longlong2*)(w0p);          // gates 0,1 @ kk
            longlong2 b0 = *(const longlong2*)(w0p + 256);    // gates 2,3 @ kk
            longlong2 a1 = *(const longlong2*)(w1p);          // gates 0,1 @ kk+1
            longlong2 b1 = *(const longlong2*)(w1p + 256);    // gates 2,3 @ kk+1
#pragma unroll
            for (int r = 0; r < TM; ++r) {
                float hv0 = (kh == 0) ? h[r].x : h[r].z;
                u64 h2 = pack2(hv0, hv0);
                acc[0][r] = ffma2(h2, (u64)a0.x, acc[0][r]);
                acc[1][r] = ffma2(h2, (u64)a0.y, acc[1][r]);
                acc[2][r] = ffma2(h2, (u64)b0.x, acc[2][r]);
                acc[3][r] = ffma2(h2, (u64)b0.y, acc[3][r]);
            }
#pragma unroll
            for (int r = 0; r < TM; ++r) {
                float hv1 = (kh == 0) ? h[r].y : h[r].w;
                u64 h2 = pack2(hv1, hv1);
                acc[0][r] = ffma2(h2, (u64)a1.x, acc[0][r]);
                acc[1][r] = ffma2(h2, (u64)a1.y, acc[1][r]);
                acc[2][r] = ffma2(h2, (u64)b1.x, acc[2][r]);
                acc[3][r] = ffma2(h2, (u64)b1.y, acc[3][r]);
            }
        }
    }
}

// SMEM layout (floats)
#define SM_H0    0
#define SM_H1    (SM_H0 + M * HSTR)
#define SM_C0    (SM_H1 + M * HSTR)
#define SM_C1    (SM_C0 + M * HSTR)
#define SM_PREV  (SM_C1 + M * HSTR)       // [M][12]
#define SM_P0    (SM_PREV + M * 12)       // [4][512]
#define SM_PRE1  (SM_P0 + NSCEN * GSZ)    // [512]
#define SM_WP    (SM_PRE1 + GSZ)          // [9][q][cg][4]; QI [4][512] overlaid (phase 1)
#define SM_WOUT  (SM_WP + NVAR * GSZ)     // [9][128]
#define SM_BOUT  (SM_WOUT + NVAR * HID)   // [16]
#define SM_SCEN  (SM_BOUT + 16)           // M ints
#define SM_FLAG  (SM_SCEN + M)
#define SM_FLOATS (SM_FLAG + 4)
#define SMEM_BYTES (SM_FLOATS * 4)

__global__ void __launch_bounds__(THREADS, 2)
lstm_kernel(const float* __restrict__ z, const int* __restrict__ scen_raw,
            const float* __restrict__ emb,
            const float* __restrict__ W_init, const float* __restrict__ b_init,
            const float* __restrict__ W_ih0,
            const float* __restrict__ b_ih0, const float* __restrict__ b_hh0,
            const float* __restrict__ b_ih1, const float* __restrict__ b_hh1,
            const float* __restrict__ W_out, const float* __restrict__ b_out,
            float* __restrict__ outp, int T) {
    extern __shared__ float sm[];
    float* sh_h0   = sm + SM_H0;
    float* sh_h1   = sm + SM_H1;
    float* sh_c0   = sm + SM_C0;
    float* sh_c1   = sm + SM_C1;
    float* sh_prev = sm + SM_PREV;
    float* sh_P0   = sm + SM_P0;
    float* sh_pre1 = sm + SM_PRE1;
    float* sh_Wp   = sm + SM_WP;      // phase 2
    float* sh_QI   = sm + SM_WP;      // phase 1 (overlay)
    float* sh_Wout = sm + SM_WOUT;
    float* sh_bout = sm + SM_BOUT;
    int*   sh_scen = (int*)(sm + SM_SCEN);
    int*   sh_flag = (int*)(sm + SM_FLAG);

    const int tid = threadIdx.x;
    const int m0  = blockIdx.x * M;

    // ---- scenario dtype detection (int64 vs int32): deterministic scan ----
    if (tid == 0) *sh_flag = 1;
    __syncthreads();
    {
        const unsigned* su = (const unsigned*)scen_raw;
        for (int k = tid; k < 512; k += THREADS)
            if (su[2 * k + 1] != 0u) *sh_flag = 0;
    }
    __syncthreads();
    const int is64 = *sh_flag;

    // ---- phase 0: tables into SMEM (QI overlaid on WP region) ----
    for (int m = tid; m < M; m += THREADS)
        sh_scen[m] = is64 ? scen_raw[2 * (m0 + m)] : scen_raw[m0 + m];
    for (int i = tid; i < NVAR * HID; i += THREADS) sh_Wout[i] = W_out[i];
    if (tid < NVAR) sh_bout[tid] = b_out[tid];
    for (int i = tid; i < GSZ; i += THREADS) sh_pre1[i] = b_ih1[i] + b_hh1[i];
    for (int i = tid; i < M * 12; i += THREADS) sh_prev[i] = 0.0f;
    for (int i = tid; i < NSCEN * GSZ; i += THREADS) {
        int s = i >> 9, j = i & (GSZ - 1);
        const float* e  = emb + s * HID;
        const float* w0 = W_ih0 + j * IH0_W + NVAR;
        const float* w1 = W_init + j * INIT_W + LAT;
        float v0 = b_ih0[j] + b_hh0[j];
        float v1 = b_init[j];
#pragma unroll 4
        for (int k = 0; k < HID; ++k) {
            float ek = e[k];
            v0 = fmaf(ek, w0[k], v0);
            v1 = fmaf(ek, w1[k], v1);
        }
        sh_P0[i] = v0;
        sh_QI[i] = v1;
    }
    __syncthreads();

    // lane mapping: warp covers 4 cgs x 8 rsubs; 16 warps cover 64 cgs
    const int lane   = tid & 31;
    const int warpid = tid >> 5;            // 0..15
    const int cgl    = lane & 3;
    const int rsub   = lane >> 2;           // 0..7
    const int cg     = warpid * 4 + cgl;    // 0..63
    const int j0     = cg * TJ;

    // thread's rows: 8*r + rsub, r = 0..3

    // ---- phase 1: h_init = z @ Wz^T + QI[scenario]  (slots: h0,c0,h1,c1) ----
    {
        float acc[4][TM][TJ];
#pragma unroll
        for (int r = 0; r < TM; ++r) {
            int s = sh_scen[8 * r + rsub];
            const float* q = sh_QI + s * GSZ + j0;
#pragma unroll
            for (int g = 0; g < 4; ++g) {
                acc[g][r][0] = q[g * HID];
                acc[g][r][1] = q[g * HID + 1];
            }
        }
        for (int k = 0; k < LAT; k += 4) {
            float4 zr[TM];
#pragma unroll
            for (int r = 0; r < TM; ++r)
                zr[r] = *(const float4*)(z + (size_t)(m0 + 8 * r + rsub) * LAT + k);
#pragma unroll
            for (int kk = 0; kk < 4; ++kk) {
                float w[4][TJ];
#pragma unroll
                for (int g = 0; g < 4; ++g)
#pragma unroll
                    for (int jj = 0; jj < TJ; ++jj)
                        w[g][jj] = W_init[(size_t)(g * HID + j0 + jj) * INIT_W + k + kk];
#pragma unroll
                for (int r = 0; r < TM; ++r) {
                    float hv = (kk == 0) ? zr[r].x : (kk == 1) ? zr[r].y
                             : (kk == 2) ? zr[r].z : zr[r].w;
#pragma unroll
                    for (int g = 0; g < 4; ++g) {
                        acc[g][r][0] = fmaf(hv, w[g][0], acc[g][r][0]);
                        acc[g][r][1] = fmaf(hv, w[g][1], acc[g][r][1]);
                    }
                }
            }
        }
#pragma unroll
        for (int r = 0; r < TM; ++r)
#pragma unroll
            for (int jj = 0; jj < TJ; ++jj) {
                int off = (8 * r + rsub) * HSTR + j0 + jj;
                sh_h0[off] = acc[0][r][jj];
                sh_c0[off] = acc[1][r][jj];
                sh_h1[off] = acc[2][r][jj];
                sh_c1[off] = acc[3][r][jj];
            }
    }
    __syncthreads();

    // ---- load WP (overwrites QI overlay): layout [v][q][cg][4] ----
    for (int i = tid; i < NVAR * GSZ; i += THREADS) {
        int v = i / GSZ, rem = i - v * GSZ;
        int q = rem >> 8, c = (rem >> 2) & 63, t = rem & 3;
        int g = q * 2 + (t >> 1), jj = t & 1;
        sh_Wp[i] = W_ih0[(g * HID + c * 2 + jj) * IH0_W + v];
    }
    __syncthreads();

    // ---- phase 2: time loop ----
    for (int t = 0; t < T; ++t) {
        u64 acc[4][TM];

        // layer0 gates: init from P0[scenario], add prev (K=9), add h0@W_hh0^T
#pragma unroll
        for (int r = 0; r < TM; ++r) {
            int s = sh_scen[8 * r + rsub];
            const float* p = sh_P0 + s * GSZ + j0;
#pragma unroll
            for (int g = 0; g < 4; ++g)
                acc[g][r] = *(const u64*)(p + g * HID);
        }
#pragma unroll
        for (int v = 0; v < NVAR; ++v) {
            const float* wr = sh_Wp + (v << 9) + (cg << 2);
            longlong2 qa = *(const longlong2*)(wr);
            longlong2 qb = *(const longlong2*)(wr + 256);
            u64 w0 = (u64)qa.x, w1 = (u64)qa.y;
            u64 w2 = (u64)qb.x, w3 = (u64)qb.y;
#pragma unroll
            for (int r = 0; r < TM; ++r) {
                float pv = sh_prev[(8 * r + rsub) * 12 + v];
                u64 p2 = pack2(pv, pv);
                acc[0][r] = ffma2(p2, w0, acc[0][r]);
                acc[1][r] = ffma2(p2, w1, acc[1][r]);
                acc[2][r] = ffma2(p2, w2, acc[2][r]);
                acc[3][r] = ffma2(p2, w3, acc[3][r]);
            }
        }
        gemm128_2(acc, g_Wt0, sh_h0, rsub, cg);
        __syncthreads();                              // S1: done reading h0

        // cell 0
#pragma unroll
        for (int r = 0; r < TM; ++r) {
            float i0, i1, f0, f1, g0, g1, o0, o1;
            unpack2(acc[0][r], i0, i1);
            unpack2(acc[1][r], f0, f1);
            unpack2(acc[2][r], g0, g1);
            unpack2(acc[3][r], o0, o1);
            int off = (8 * r + rsub) * HSTR + j0;
            float c0n = sigf(f0) * sh_c0[off]     + sigf(i0) * tanh_fast(g0);
            float c1n = sigf(f1) * sh_c0[off + 1] + sigf(i1) * tanh_fast(g1);
            sh_c0[off]     = c0n;
            sh_c0[off + 1] = c1n;
            sh_h0[off]     = sigf(o0) * tanh_fast(c0n);
            sh_h0[off + 1] = sigf(o1) * tanh_fast(c1n);
        }
        __syncthreads();                              // S2: h0n visible

        // layer1 gates: pre1 + h0n@W_ih1^T + h1@W_hh1^T
#pragma unroll
        for (int r = 0; r < TM; ++r)
#pragma unroll
            for (int g = 0; g < 4; ++g)
                acc[g][r] = *(const u64*)(sh_pre1 + g * HID + j0);
        gemm128_2(acc, g_Wt1, sh_h0, rsub, cg);
        gemm128_2(acc, g_Wt1 + HID * GSZ, sh_h1, rsub, cg);
        __syncthreads();                              // S3: done reading h1

        // cell 1
#pragma unroll
        for (int r = 0; r < TM; ++r) {
            float i0, i1, f0, f1, g0, g1, o0, o1;
            unpack2(acc[0][r], i0, i1);
            unpack2(acc[1][r], f0, f1);
            unpack2(acc[2][r], g0, g1);
            unpack2(acc[3][r], o0, o1);
            int off = (8 * r + rsub) * HSTR + j0;
            float c0n = sigf(f0) * sh_c1[off]     + sigf(i0) * tanh_fast(g0);
            float c1n = sigf(f1) * sh_c1[off + 1] + sigf(i1) * tanh_fast(g1);
            sh_c1[off]     = c0n;
            sh_c1[off + 1] = c1n;
            sh_h1[off]     = sigf(o0) * tanh_fast(c0n);
            sh_h1[off + 1] = sigf(o1) * tanh_fast(c1n);
        }
        __syncthreads();                              // S4: h1n visible

        // output head: out = h1n @ W_out^T + b_out ; also becomes prev
        if (tid < M * NVAR) {
            int m = tid / NVAR, v = tid - m * NVAR;
            const float* hrow = sh_h1 + m * HSTR;
            const float* wrow = sh_Wout + v * HID;
            float s0 = sh_bout[v], s1 = 0.f, s2 = 0.f, s3 = 0.f;
#pragma unroll 8
            for (int k = 0; k < HID; k += 4) {
                s0 = fmaf(hrow[k],     wrow[k],     s0);
                s1 = fmaf(hrow[k + 1], wrow[k + 1], s1);
                s2 = fmaf(hrow[k + 2], wrow[k + 2], s2);
                s3 = fmaf(hrow[k + 3], wrow[k + 3], s3);
            }
            float s = (s0 + s1) + (s2 + s3);
            sh_prev[m * 12 + v] = s;
            outp[((size_t)(m0 + m) * T + t) * NVAR + v] = s;
        }
        __syncthreads();                              // S5: prev visible
    }
}

extern "C" void kernel_launch(void* const* d_in, const int* in_sizes, int n_in,
                              void* d_out, int out_size) {
    // input order: z, scenario, [seq_length], emb, W_init, b_init, W_ih0, W_hh0,
    //              b_ih0, b_hh0, W_ih1, W_hh1, b_ih1, b_hh1, W_out, b_out
    int off = (n_in >= 16) ? 1 : 0;   // seq_length scalar present or not
    const float* z      = (const float*)d_in[0];
    const int*   scen   = (const int*)d_in[1];
    const float* emb    = (const float*)d_in[2 + off];
    const float* W_init = (const float*)d_in[3 + off];
    const float* b_init = (const float*)d_in[4 + off];
    const float* W_ih0  = (const float*)d_in[5 + off];
    const float* W_hh0  = (const float*)d_in[6 + off];
    const float* b_ih0  = (const float*)d_in[7 + off];
    const float* b_hh0  = (const float*)d_in[8 + off];
    const float* W_ih1  = (const float*)d_in[9 + off];
    const float* W_hh1  = (const float*)d_in[10 + off];
    const float* b_ih1  = (const float*)d_in[11 + off];
    const float* b_hh1  = (const float*)d_in[12 + off];
    const float* W_out  = (const float*)d_in[13 + off];
    const float* b_out  = (const float*)d_in[14 + off];
    float* outp = (float*)d_out;

    int B = in_sizes[0] / LAT;
    int T = out_size / (B * NVAR);

    cudaFuncSetAttribute(lstm_kernel,
                         cudaFuncAttributeMaxDynamicSharedMemorySize, SMEM_BYTES);

    transpose_kernel<<<(HID * GSZ + 255) / 256, 256>>>(W_hh0, W_ih1, W_hh1);
    lstm_kernel<<<B / M, THREADS, SMEM_BYTES>>>(
        z, scen, emb, W_init, b_init, W_ih0,
        b_ih0, b_hh0, b_ih1, b_hh1, W_out, b_out, outp, T);
}

// round 12
// speedup vs baseline: 1.4296x; 1.4296x over previous
#include <cuda_runtime.h>
#include <cuda_bf16.h>

#define LAT     32
#define HID     128
#define HSTR    132     // padded row stride (floats)
#define GSZ     512     // 4*HID
#define NVAR    9
#define NSCEN   4
#define IH0_W   (NVAR + HID)   // 137
#define INIT_W  (LAT + HID)    // 160

#define M       32      // batch rows per CTA
#define THREADS 256
#define TM      8       // rows per thread (rows 4*r + rsub)
#define TJ      2       // hidden units per thread (one f32x2 pair)

typedef unsigned long long u64;

// -------- device scratch: weights relaid out [k][q][cg][4] --------
__device__ __align__(16) float g_Wt0[HID * GSZ];        // W_hh0
__device__ __align__(16) float g_Wt1[2 * HID * GSZ];    // k<128: W_ih1, k>=128: W_hh1

__global__ void transpose_kernel(const float* __restrict__ W_hh0,
                                 const float* __restrict__ W_ih1,
                                 const float* __restrict__ W_hh1) {
    int i = blockIdx.x * blockDim.x + threadIdx.x;   // i = k*512 + col
    if (i >= HID * GSZ) return;
    int k = i >> 9, col = i & (GSZ - 1);
    int g = col >> 7, w = col & 127;
    int cg = w >> 1, jj = w & 1;
    int dst = (k << 9) + ((g >> 1) << 8) + (cg << 2) + ((g & 1) << 1) + jj;
    g_Wt0[dst]             = W_hh0[col * HID + k];
    g_Wt1[dst]             = W_ih1[col * HID + k];
    g_Wt1[HID * GSZ + dst] = W_hh1[col * HID + k];
}

__device__ __forceinline__ float sigf(float x) {
    return __fdividef(1.0f, 1.0f + __expf(-x));
}
__device__ __forceinline__ float tanh_fast(float x) {
    return __fdividef(2.0f, 1.0f + __expf(-2.0f * x)) - 1.0f;
}

// ---- packed fp32x2 helpers (sm_103a FFMA2 path) ----
__device__ __forceinline__ u64 pack2(float lo, float hi) {
    u64 d;
    asm("mov.b64 %0, {%1, %2};" : "=l"(d) : "f"(lo), "f"(hi));
    return d;
}
__device__ __forceinline__ void unpack2(u64 v, float& lo, float& hi) {
    asm("mov.b64 {%0, %1}, %2;" : "=f"(lo), "=f"(hi) : "l"(v));
}
__device__ __forceinline__ u64 ffma2(u64 a, u64 b, u64 c) {
    u64 d;
    asm("fma.rn.f32x2 %0, %1, %2, %3;" : "=l"(d) : "l"(a), "l"(b), "l"(c));
    return d;
}

// acc[g][r] (+)= shH[4r+rsub][k] * W[k][col-pair cg], K = 128, packed pairs.
// Warp covers 8 disjoint cgs x 4 rsubs -> each weight byte read ONCE per CTA.
__device__ __forceinline__ void gemm128_2(u64 acc[4][TM],
                                          const float* __restrict__ Wt,
                                          const float* __restrict__ shH,
                                          int rsub, int cg) {
    const float* wbase = Wt + (cg << 2);
    const float* hbase = shH + rsub * HSTR;
#pragma unroll 2
    for (int k = 0; k < HID; k += 4) {
        float4 h[TM];
#pragma unroll
        for (int r = 0; r < TM; ++r)
            h[r] = *(const float4*)(hbase + r * (4 * HSTR) + k);
#pragma unroll
        for (int kh = 0; kh < 4; kh += 2) {
            const float* w0p = wbase + ((k + kh) << 9);
            const float* w1p = wbase + ((k + kh + 1) << 9);
            longlong2 a0 = *(const longlong2*)(w0p);          // gates 0,1 @ kk
            longlong2 b0 = *(const longlong2*)(w0p + 256);    // gates 2,3 @ kk
            longlong2 a1 = *(const longlong2*)(w1p);          // gates 0,1 @ kk+1
            longlong2 b1 = *(const longlong2*)(w1p + 256);    // gates 2,3 @ kk+1
#pragma unroll
            for (int r = 0; r < TM; ++r) {
                float hv0 = (kh == 0) ? h[r].x : h[r].z;
                u64 h2 = pack2(hv0, hv0);
                acc[0][r] = ffma2(h2, (u64)a0.x, acc[0][r]);
                acc[1][r] = ffma2(h2, (u64)a0.y, acc[1][r]);
                acc[2][r] = ffma2(h2, (u64)b0.x, acc[2][r]);
                acc[3][r] = ffma2(h2, (u64)b0.y, acc[3][r]);
            }
#pragma unroll
            for (int r = 0; r < TM; ++r) {
                float hv1 = (kh == 0) ? h[r].y : h[r].w;
                u64 h2 = pack2(hv1, hv1);
                acc[0][r] = ffma2(h2, (u64)a1.x, acc[0][r]);
                acc[1][r] = ffma2(h2, (u64)a1.y, acc[1][r]);
                acc[2][r] = ffma2(h2, (u64)b1.x, acc[2][r]);
                acc[3][r] = ffma2(h2, (u64)b1.y, acc[3][r]);
            }
        }
    }
}

// SMEM layout (floats): h double-buffered, c lives in registers
#define SM_H0A   0
#define SM_H0B   (SM_H0A + M * HSTR)
#define SM_H1A   (SM_H0B + M * HSTR)
#define SM_H1B   (SM_H1A + M * HSTR)
#define SM_PREV  (SM_H1B + M * HSTR)      // [M][12]
#define SM_P0    (SM_PREV + M * 12)       // [4][512]
#define SM_PRE1  (SM_P0 + NSCEN * GSZ)    // [512]
#define SM_WP    (SM_PRE1 + GSZ)          // [9][q][cg][4]; QI [4][512] overlaid (phase 1)
#define SM_WOUT  (SM_WP + NVAR * GSZ)     // [9][128]
#define SM_BOUT  (SM_WOUT + NVAR * HID)   // [16]
#define SM_SCEN  (SM_BOUT + 16)           // M ints
#define SM_FLAG  (SM_SCEN + M)
#define SM_FLOATS (SM_FLAG + 4)
#define SMEM_BYTES (SM_FLOATS * 4)

__global__ void __launch_bounds__(THREADS, 2)
lstm_kernel(const float* __restrict__ z, const int* __restrict__ scen_raw,
            const float* __restrict__ emb,
            const float* __restrict__ W_init, const float* __restrict__ b_init,
            const float* __restrict__ W_ih0,
            const float* __restrict__ b_ih0, const float* __restrict__ b_hh0,
            const float* __restrict__ b_ih1, const float* __restrict__ b_hh1,
            const float* __restrict__ W_out, const float* __restrict__ b_out,
            float* __restrict__ outp, int T) {
    extern __shared__ float sm[];
    float* sh_prev = sm + SM_PREV;
    float* sh_P0   = sm + SM_P0;
    float* sh_pre1 = sm + SM_PRE1;
    float* sh_Wp   = sm + SM_WP;      // phase 2
    float* sh_QI   = sm + SM_WP;      // phase 1 (overlay)
    float* sh_Wout = sm + SM_WOUT;
    float* sh_bout = sm + SM_BOUT;
    int*   sh_scen = (int*)(sm + SM_SCEN);
    int*   sh_flag = (int*)(sm + SM_FLAG);

    const int tid = threadIdx.x;
    const int m0  = blockIdx.x * M;

    // ---- scenario dtype detection (int64 vs int32): deterministic scan ----
    if (tid == 0) *sh_flag = 1;
    __syncthreads();
    {
        const unsigned* su = (const unsigned*)scen_raw;
        for (int k = tid; k < 512; k += THREADS)
            if (su[2 * k + 1] != 0u) *sh_flag = 0;
    }
    __syncthreads();
    const int is64 = *sh_flag;

    // ---- phase 0: tables into SMEM (QI overlaid on WP region) ----
    for (int m = tid; m < M; m += THREADS)
        sh_scen[m] = is64 ? scen_raw[2 * (m0 + m)] : scen_raw[m0 + m];
    for (int i = tid; i < NVAR * HID; i += THREADS) sh_Wout[i] = W_out[i];
    if (tid < NVAR) sh_bout[tid] = b_out[tid];
    for (int i = tid; i < GSZ; i += THREADS) sh_pre1[i] = b_ih1[i] + b_hh1[i];
    for (int i = tid; i < M * 12; i += THREADS) sh_prev[i] = 0.0f;
    for (int i = tid; i < NSCEN * GSZ; i += THREADS) {
        int s = i >> 9, j = i & (GSZ - 1);
        const float* e  = emb + s * HID;
        const float* w0 = W_ih0 + j * IH0_W + NVAR;
        const float* w1 = W_init + j * INIT_W + LAT;
        float v0 = b_ih0[j] + b_hh0[j];
        float v1 = b_init[j];
#pragma unroll 4
        for (int k = 0; k < HID; ++k) {
            float ek = e[k];
            v0 = fmaf(ek, w0[k], v0);
            v1 = fmaf(ek, w1[k], v1);
        }
        sh_P0[i] = v0;
        sh_QI[i] = v1;
    }
    __syncthreads();

    // lane mapping: warp covers 8 cgs x 4 rsubs
    const int lane   = tid & 31;
    const int warpid = tid >> 5;            // 0..7
    const int cgl    = lane & 7;
    const int rsub   = lane >> 3;           // 0..3
    const int cg     = warpid * 8 + cgl;    // 0..63
    const int j0     = cg * TJ;

    // thread's rows: 4*r + rsub, r = 0..7 ; cell state lives in registers
    float c0r[TM][2], c1r[TM][2];

    // ---- phase 1: h_init = z @ Wz^T + QI[scenario]  (h0,c0,h1,c1) ----
    {
        float acc[4][TM][TJ];
#pragma unroll
        for (int r = 0; r < TM; ++r) {
            int s = sh_scen[4 * r + rsub];
            const float* q = sh_QI + s * GSZ + j0;
#pragma unroll
            for (int g = 0; g < 4; ++g) {
                acc[g][r][0] = q[g * HID];
                acc[g][r][1] = q[g * HID + 1];
            }
        }
        for (int k = 0; k < LAT; k += 4) {
            float4 zr[TM];
#pragma unroll
            for (int r = 0; r < TM; ++r)
                zr[r] = *(const float4*)(z + (size_t)(m0 + 4 * r + rsub) * LAT + k);
#pragma unroll
            for (int kk = 0; kk < 4; ++kk) {
                float w[4][TJ];
#pragma unroll
                for (int g = 0; g < 4; ++g)
#pragma unroll
                    for (int jj = 0; jj < TJ; ++jj)
                        w[g][jj] = W_init[(size_t)(g * HID + j0 + jj) * INIT_W + k + kk];
#pragma unroll
                for (int r = 0; r < TM; ++r) {
                    float hv = (kk == 0) ? zr[r].x : (kk == 1) ? zr[r].y
                             : (kk == 2) ? zr[r].z : zr[r].w;
#pragma unroll
                    for (int g = 0; g < 4; ++g) {
                        acc[g][r][0] = fmaf(hv, w[g][0], acc[g][r][0]);
                        acc[g][r][1] = fmaf(hv, w[g][1], acc[g][r][1]);
                    }
                }
            }
        }
#pragma unroll
        for (int r = 0; r < TM; ++r)
#pragma unroll
            for (int jj = 0; jj < TJ; ++jj) {
                int off = (4 * r + rsub) * HSTR + j0 + jj;
                sm[SM_H0A + off] = acc[0][r][jj];   // h0 -> buffer A
                c0r[r][jj]       = acc[1][r][jj];   // c0 -> regs
                sm[SM_H1A + off] = acc[2][r][jj];   // h1 -> buffer A
                c1r[r][jj]       = acc[3][r][jj];   // c1 -> regs
            }
    }
    __syncthreads();

    // ---- load WP (overwrites QI overlay): layout [v][q][cg][4] ----
    for (int i = tid; i < NVAR * GSZ; i += THREADS) {
        int v = i / GSZ, rem = i - v * GSZ;
        int q = rem >> 8, c = (rem >> 2) & 63, t = rem & 3;
        int g = q * 2 + (t >> 1), jj = t & 1;
        sh_Wp[i] = W_ih0[(g * HID + c * 2 + jj) * IH0_W + v];
    }
    __syncthreads();

    // ---- phase 2: time loop, 3 barriers/step via h ping-pong ----
    float* h0c = sm + SM_H0A;  float* h0n = sm + SM_H0B;
    float* h1c = sm + SM_H1A;  float* h1n = sm + SM_H1B;

    for (int t = 0; t < T; ++t) {
        u64 acc[4][TM];

        // layer0 gates: init from P0[scenario], add prev (K=9), add h0c@W_hh0^T
#pragma unroll
        for (int r = 0; r < TM; ++r) {
            int s = sh_scen[4 * r + rsub];
            const float* p = sh_P0 + s * GSZ + j0;
#pragma unroll
            for (int g = 0; g < 4; ++g)
                acc[g][r] = *(const u64*)(p + g * HID);
        }
#pragma unroll
        for (int v = 0; v < NVAR; ++v) {
            const float* wr = sh_Wp + (v << 9) + (cg << 2);
            longlong2 qa = *(const longlong2*)(wr);
            longlong2 qb = *(const longlong2*)(wr + 256);
            u64 w0 = (u64)qa.x, w1 = (u64)qa.y;
            u64 w2 = (u64)qb.x, w3 = (u64)qb.y;
#pragma unroll
            for (int r = 0; r < TM; ++r) {
                float pv = sh_prev[(4 * r + rsub) * 12 + v];
                u64 p2 = pack2(pv, pv);
                acc[0][r] = ffma2(p2, w0, acc[0][r]);
                acc[1][r] = ffma2(p2, w1, acc[1][r]);
                acc[2][r] = ffma2(p2, w2, acc[2][r]);
                acc[3][r] = ffma2(p2, w3, acc[3][r]);
            }
        }
        gemm128_2(acc, g_Wt0, h0c, rsub, cg);

        // cell 0: c in regs, h0_new -> alternate buffer (no WAR barrier)
#pragma unroll
        for (int r = 0; r < TM; ++r) {
            float i0, i1, f0, f1, g0, g1, o0, o1;
            unpack2(acc[0][r], i0, i1);
            unpack2(acc[1][r], f0, f1);
            unpack2(acc[2][r], g0, g1);
            unpack2(acc[3][r], o0, o1);
            int off = (4 * r + rsub) * HSTR + j0;
            float c0n = sigf(f0) * c0r[r][0] + sigf(i0) * tanh_fast(g0);
            float c1n = sigf(f1) * c0r[r][1] + sigf(i1) * tanh_fast(g1);
            c0r[r][0] = c0n;
            c0r[r][1] = c1n;
            h0n[off]     = sigf(o0) * tanh_fast(c0n);
            h0n[off + 1] = sigf(o1) * tanh_fast(c1n);
        }
        __syncthreads();                              // B1: h0n visible

        // layer1 gates: pre1 + h0n@W_ih1^T + h1c@W_hh1^T
#pragma unroll
        for (int r = 0; r < TM; ++r)
#pragma unroll
            for (int g = 0; g < 4; ++g)
                acc[g][r] = *(const u64*)(sh_pre1 + g * HID + j0);
        gemm128_2(acc, g_Wt1, h0n, rsub, cg);
        gemm128_2(acc, g_Wt1 + HID * GSZ, h1c, rsub, cg);

        // cell 1
#pragma unroll
        for (int r = 0; r < TM; ++r) {
            float i0, i1, f0, f1, g0, g1, o0, o1;
            unpack2(acc[0][r], i0, i1);
            unpack2(acc[1][r], f0, f1);
            unpack2(acc[2][r], g0, g1);
            unpack2(acc[3][r], o0, o1);
            int off = (4 * r + rsub) * HSTR + j0;
            float c0n = sigf(f0) * c1r[r][0] + sigf(i0) * tanh_fast(g0);
            float c1n = sigf(f1) * c1r[r][1] + sigf(i1) * tanh_fast(g1);
            c1r[r][0] = c0n;
            c1r[r][1] = c1n;
            h1n[off]     = sigf(o0) * tanh_fast(c0n);
            h1n[off + 1] = sigf(o1) * tanh_fast(c1n);
        }
        __syncthreads();                              // B2: h1n visible

        // output head: out = h1n @ W_out^T + b_out ; also becomes prev
        for (int idx = tid; idx < M * NVAR; idx += THREADS) {
            int m = idx / NVAR, v = idx - m * NVAR;
            const float* hrow = h1n + m * HSTR;
            const float* wrow = sh_Wout + v * HID;
            float s0 = sh_bout[v], s1 = 0.f, s2 = 0.f, s3 = 0.f;
#pragma unroll 8
            for (int k = 0; k < HID; k += 4) {
                s0 = fmaf(hrow[k],     wrow[k],     s0);
                s1 = fmaf(hrow[k + 1], wrow[k + 1], s1);
                s2 = fmaf(hrow[k + 2], wrow[k + 2], s2);
                s3 = fmaf(hrow[k + 3], wrow[k + 3], s3);
            }
            float s = (s0 + s1) + (s2 + s3);
            sh_prev[m * 12 + v] = s;
            outp[((size_t)(m0 + m) * T + t) * NVAR + v] = s;
        }
        __syncthreads();                              // B3: prev visible

        // swap ping-pong buffers
        float* tmp;
        tmp = h0c; h0c = h0n; h0n = tmp;
        tmp = h1c; h1c = h1n; h1n = tmp;
    }
}

extern "C" void kernel_launch(void* const* d_in, const int* in_sizes, int n_in,
                              void* d_out, int out_size) {
    // input order: z, scenario, [seq_length], emb, W_init, b_init, W_ih0, W_hh0,
    //              b_ih0, b_hh0, W_ih1, W_hh1, b_ih1, b_hh1, W_out, b_out
    int off = (n_in >= 16) ? 1 : 0;   // seq_length scalar present or not
    const float* z      = (const float*)d_in[0];
    const int*   scen   = (const int*)d_in[1];
    const float* emb    = (const float*)d_in[2 + off];
    const float* W_init = (const float*)d_in[3 + off];
    const float* b_init = (const float*)d_in[4 + off];
    const float* W_ih0  = (const float*)d_in[5 + off];
    const float* W_hh0  = (const float*)d_in[6 + off];
    const float* b_ih0  = (const float*)d_in[7 + off];
    const float* b_hh0  = (const float*)d_in[8 + off];
    const float* W_ih1  = (const float*)d_in[9 + off];
    const float* W_hh1  = (const float*)d_in[10 + off];
    const float* b_ih1  = (const float*)d_in[11 + off];
    const float* b_hh1  = (const float*)d_in[12 + off];
    const float* W_out  = (const float*)d_in[13 + off];
    const float* b_out  = (const float*)d_in[14 + off];
    float* outp = (float*)d_out;

    int B = in_sizes[0] / LAT;
    int T = out_size / (B * NVAR);

    cudaFuncSetAttribute(lstm_kernel,
                         cudaFuncAttributeMaxDynamicSharedMemorySize, SMEM_BYTES);

    transpose_kernel<<<(HID * GSZ + 255) / 256, 256>>>(W_hh0, W_ih1, W_hh1);
    lstm_kernel<<<B / M, THREADS, SMEM_BYTES>>>(
        z, scen, emb, W_init, b_init, W_ih0,
        b_ih0, b_hh0, b_ih1, b_hh1, W_out, b_out, outp, T);
}

// round 13
// speedup vs baseline: 1.4303x; 1.0005x over previous
#include <cuda_runtime.h>
#include <cuda_bf16.h>

#define LAT     32
#define HID     128
#define HSTR    132     // padded row stride (floats)
#define GSZ     512     // 4*HID
#define NVAR    9
#define NSCEN   4
#define IH0_W   (NVAR + HID)   // 137
#define INIT_W  (LAT + HID)    // 160

#define M       32      // batch rows per CTA
#define THREADS 256
#define TM      8       // rows per thread (rows 4*r + rsub)
#define TJ      2       // hidden units per thread (one f32x2 pair)

typedef unsigned long long u64;

// -------- device scratch: weights relaid out [k][q][cg][4] --------
__device__ __align__(16) float g_Wt0[HID * GSZ];        // W_hh0
__device__ __align__(16) float g_Wt1[2 * HID * GSZ];    // k<128: W_ih1, k>=128: W_hh1

__global__ void transpose_kernel(const float* __restrict__ W_hh0,
                                 const float* __restrict__ W_ih1,
                                 const float* __restrict__ W_hh1) {
    int i = blockIdx.x * blockDim.x + threadIdx.x;   // i = k*512 + col
    if (i >= HID * GSZ) return;
    int k = i >> 9, col = i & (GSZ - 1);
    int g = col >> 7, w = col & 127;
    int cg = w >> 1, jj = w & 1;
    int dst = (k << 9) + ((g >> 1) << 8) + (cg << 2) + ((g & 1) << 1) + jj;
    g_Wt0[dst]             = W_hh0[col * HID + k];
    g_Wt1[dst]             = W_ih1[col * HID + k];
    g_Wt1[HID * GSZ + dst] = W_hh1[col * HID + k];
}

__device__ __forceinline__ float sigf(float x) {
    return __fdividef(1.0f, 1.0f + __expf(-x));
}
__device__ __forceinline__ float tanh_fast(float x) {
    return __fdividef(2.0f, 1.0f + __expf(-2.0f * x)) - 1.0f;
}

// ---- packed fp32x2 helpers (sm_103a FFMA2 path) ----
__device__ __forceinline__ u64 pack2(float lo, float hi) {
    u64 d;
    asm("mov.b64 %0, {%1, %2};" : "=l"(d) : "f"(lo), "f"(hi));
    return d;
}
__device__ __forceinline__ void unpack2(u64 v, float& lo, float& hi) {
    asm("mov.b64 {%0, %1}, %2;" : "=f"(lo), "=f"(hi) : "l"(v));
}
__device__ __forceinline__ u64 ffma2(u64 a, u64 b, u64 c) {
    u64 d;
    asm("fma.rn.f32x2 %0, %1, %2, %3;" : "=l"(d) : "l"(a), "l"(b), "l"(c));
    return d;
}

// acc[g][r] (+)= shH[4r+rsub][k] * W[k][col-pair cg], K = 128, packed pairs.
// Warp covers 8 disjoint cgs x 4 rsubs -> each weight byte read ONCE per CTA.
__device__ __forceinline__ void gemm128_2(u64 acc[4][TM],
                                          const float* __restrict__ Wt,
                                          const float* __restrict__ shH,
                                          int rsub, int cg) {
    const float* wbase = Wt + (cg << 2);
    const float* hbase = shH + rsub * HSTR;
#pragma unroll 2
    for (int k = 0; k < HID; k += 4) {
        float4 h[TM];
#pragma unroll
        for (int r = 0; r < TM; ++r)
            h[r] = *(const float4*)(hbase + r * (4 * HSTR) + k);
#pragma unroll
        for (int kh = 0; kh < 4; kh += 2) {
            const float* w0p = wbase + ((k + kh) << 9);
            const float* w1p = wbase + ((k + kh + 1) << 9);
            longlong2 a0 = *(const longlong2*)(w0p);          // gates 0,1 @ kk
            longlong2 b0 = *(const longlong2*)(w0p + 256);    // gates 2,3 @ kk
            longlong2 a1 = *(const longlong2*)(w1p);          // gates 0,1 @ kk+1
            longlong2 b1 = *(const longlong2*)(w1p + 256);    // gates 2,3 @ kk+1
#pragma unroll
            for (int r = 0; r < TM; ++r) {
                float hv0 = (kh == 0) ? h[r].x : h[r].z;
                u64 h2 = pack2(hv0, hv0);
                acc[0][r] = ffma2(h2, (u64)a0.x, acc[0][r]);
                acc[1][r] = ffma2(h2, (u64)a0.y, acc[1][r]);
                acc[2][r] = ffma2(h2, (u64)b0.x, acc[2][r]);
                acc[3][r] = ffma2(h2, (u64)b0.y, acc[3][r]);
            }
#pragma unroll
            for (int r = 0; r < TM; ++r) {
                float hv1 = (kh == 0) ? h[r].y : h[r].w;
                u64 h2 = pack2(hv1, hv1);
                acc[0][r] = ffma2(h2, (u64)a1.x, acc[0][r]);
                acc[1][r] = ffma2(h2, (u64)a1.y, acc[1][r]);
                acc[2][r] = ffma2(h2, (u64)b1.x, acc[2][r]);
                acc[3][r] = ffma2(h2, (u64)b1.y, acc[3][r]);
            }
        }
    }
}

// SMEM layout (floats): h double-buffered, c lives in registers
#define SM_H0A   0
#define SM_H0B   (SM_H0A + M * HSTR)
#define SM_H1A   (SM_H0B + M * HSTR)
#define SM_H1B   (SM_H1A + M * HSTR)
#define SM_PREV  (SM_H1B + M * HSTR)      // [M][12]
#define SM_P0    (SM_PREV + M * 12)       // [4][512]
#define SM_PRE1  (SM_P0 + NSCEN * GSZ)    // [512]
#define SM_WP    (SM_PRE1 + GSZ)          // [9][q][cg][4]; QI [4][512] overlaid (phase 1)
#define SM_WOUT  (SM_WP + NVAR * GSZ)     // [9][128]
#define SM_BOUT  (SM_WOUT + NVAR * HID)   // [16]
#define SM_SCEN  (SM_BOUT + 16)           // M ints
#define SM_FLAG  (SM_SCEN + M)
#define SM_FLOATS (SM_FLAG + 4)
#define SMEM_BYTES (SM_FLOATS * 4)

__global__ void __launch_bounds__(THREADS, 2)
lstm_kernel(const float* __restrict__ z, const int* __restrict__ scen_raw,
            const float* __restrict__ emb,
            const float* __restrict__ W_init, const float* __restrict__ b_init,
            const float* __restrict__ W_ih0,
            const float* __restrict__ b_ih0, const float* __restrict__ b_hh0,
            const float* __restrict__ b_ih1, const float* __restrict__ b_hh1,
            const float* __restrict__ W_out, const float* __restrict__ b_out,
            float* __restrict__ outp, int T) {
    extern __shared__ float sm[];
    float* sh_prev = sm + SM_PREV;
    float* sh_P0   = sm + SM_P0;
    float* sh_pre1 = sm + SM_PRE1;
    float* sh_Wp   = sm + SM_WP;      // phase 2
    float* sh_QI   = sm + SM_WP;      // phase 1 (overlay)
    float* sh_Wout = sm + SM_WOUT;
    float* sh_bout = sm + SM_BOUT;
    int*   sh_scen = (int*)(sm + SM_SCEN);
    int*   sh_flag = (int*)(sm + SM_FLAG);

    const int tid = threadIdx.x;
    const int m0  = blockIdx.x * M;

    // ---- scenario dtype detection (int64 vs int32): deterministic scan ----
    if (tid == 0) *sh_flag = 1;
    __syncthreads();
    {
        const unsigned* su = (const unsigned*)scen_raw;
        for (int k = tid; k < 512; k += THREADS)
            if (su[2 * k + 1] != 0u) *sh_flag = 0;
    }
    __syncthreads();
    const int is64 = *sh_flag;

    // ---- phase 0: tables into SMEM (QI overlaid on WP region) ----
    for (int m = tid; m < M; m += THREADS)
        sh_scen[m] = is64 ? scen_raw[2 * (m0 + m)] : scen_raw[m0 + m];
    for (int i = tid; i < NVAR * HID; i += THREADS) sh_Wout[i] = W_out[i];
    if (tid < NVAR) sh_bout[tid] = b_out[tid];
    for (int i = tid; i < GSZ; i += THREADS) sh_pre1[i] = b_ih1[i] + b_hh1[i];
    for (int i = tid; i < M * 12; i += THREADS) sh_prev[i] = 0.0f;
    for (int i = tid; i < NSCEN * GSZ; i += THREADS) {
        int s = i >> 9, j = i & (GSZ - 1);
        const float* e  = emb + s * HID;
        const float* w0 = W_ih0 + j * IH0_W + NVAR;
        const float* w1 = W_init + j * INIT_W + LAT;
        float v0 = b_ih0[j] + b_hh0[j];
        float v1 = b_init[j];
#pragma unroll 4
        for (int k = 0; k < HID; ++k) {
            float ek = e[k];
            v0 = fmaf(ek, w0[k], v0);
            v1 = fmaf(ek, w1[k], v1);
        }
        sh_P0[i] = v0;
        sh_QI[i] = v1;
    }
    __syncthreads();

    // lane mapping: warp covers 8 cgs x 4 rsubs
    const int lane   = tid & 31;
    const int warpid = tid >> 5;            // 0..7
    const int cgl    = lane & 7;
    const int rsub   = lane >> 3;           // 0..3
    const int cg     = warpid * 8 + cgl;    // 0..63
    const int j0     = cg * TJ;

    // thread's rows: 4*r + rsub, r = 0..7 ; cell state lives in registers
    float c0r[TM][2], c1r[TM][2];

    // ---- phase 1: h_init = z @ Wz^T + QI[scenario]  (h0,c0,h1,c1) ----
    {
        float acc[4][TM][TJ];
#pragma unroll
        for (int r = 0; r < TM; ++r) {
            int s = sh_scen[4 * r + rsub];
            const float* q = sh_QI + s * GSZ + j0;
#pragma unroll
            for (int g = 0; g < 4; ++g) {
                acc[g][r][0] = q[g * HID];
                acc[g][r][1] = q[g * HID + 1];
            }
        }
        for (int k = 0; k < LAT; k += 4) {
            float4 zr[TM];
#pragma unroll
            for (int r = 0; r < TM; ++r)
                zr[r] = *(const float4*)(z + (size_t)(m0 + 4 * r + rsub) * LAT + k);
#pragma unroll
            for (int kk = 0; kk < 4; ++kk) {
                float w[4][TJ];
#pragma unroll
                for (int g = 0; g < 4; ++g)
#pragma unroll
                    for (int jj = 0; jj < TJ; ++jj)
                        w[g][jj] = W_init[(size_t)(g * HID + j0 + jj) * INIT_W + k + kk];
#pragma unroll
                for (int r = 0; r < TM; ++r) {
                    float hv = (kk == 0) ? zr[r].x : (kk == 1) ? zr[r].y
                             : (kk == 2) ? zr[r].z : zr[r].w;
#pragma unroll
                    for (int g = 0; g < 4; ++g) {
                        acc[g][r][0] = fmaf(hv, w[g][0], acc[g][r][0]);
                        acc[g][r][1] = fmaf(hv, w[g][1], acc[g][r][1]);
                    }
                }
            }
        }
#pragma unroll
        for (int r = 0; r < TM; ++r)
#pragma unroll
            for (int jj = 0; jj < TJ; ++jj) {
                int off = (4 * r + rsub) * HSTR + j0 + jj;
                sm[SM_H0A + off] = acc[0][r][jj];   // h0 -> buffer A
                c0r[r][jj]       = acc[1][r][jj];   // c0 -> regs
                sm[SM_H1A + off] = acc[2][r][jj];   // h1 -> buffer A
                c1r[r][jj]       = acc[3][r][jj];   // c1 -> regs
            }
    }
    __syncthreads();

    // ---- load WP (overwrites QI overlay): layout [v][q][cg][4] ----
    for (int i = tid; i < NVAR * GSZ; i += THREADS) {
        int v = i / GSZ, rem = i - v * GSZ;
        int q = rem >> 8, c = (rem >> 2) & 63, t = rem & 3;
        int g = q * 2 + (t >> 1), jj = t & 1;
        sh_Wp[i] = W_ih0[(g * HID + c * 2 + jj) * IH0_W + v];
    }
    __syncthreads();

    // ---- phase 2: time loop, 3 barriers/step via h ping-pong ----
    float* h0c = sm + SM_H0A;  float* h0n = sm + SM_H0B;
    float* h1c = sm + SM_H1A;  float* h1n = sm + SM_H1B;

    for (int t = 0; t < T; ++t) {
        u64 acc[4][TM];

        // layer0 gates: init from P0[scenario], add prev (K=9), add h0c@W_hh0^T
#pragma unroll
        for (int r = 0; r < TM; ++r) {
            int s = sh_scen[4 * r + rsub];
            const float* p = sh_P0 + s * GSZ + j0;
#pragma unroll
            for (int g = 0; g < 4; ++g)
                acc[g][r] = *(const u64*)(p + g * HID);
        }
#pragma unroll
        for (int v = 0; v < NVAR; ++v) {
            const float* wr = sh_Wp + (v << 9) + (cg << 2);
            longlong2 qa = *(const longlong2*)(wr);
            longlong2 qb = *(const longlong2*)(wr + 256);
            u64 w0 = (u64)qa.x, w1 = (u64)qa.y;
            u64 w2 = (u64)qb.x, w3 = (u64)qb.y;
#pragma unroll
            for (int r = 0; r < TM; ++r) {
                float pv = sh_prev[(4 * r + rsub) * 12 + v];
                u64 p2 = pack2(pv, pv);
                acc[0][r] = ffma2(p2, w0, acc[0][r]);
                acc[1][r] = ffma2(p2, w1, acc[1][r]);
                acc[2][r] = ffma2(p2, w2, acc[2][r]);
                acc[3][r] = ffma2(p2, w3, acc[3][r]);
            }
        }
        gemm128_2(acc, g_Wt0, h0c, rsub, cg);

        // cell 0: c in regs, h0_new -> alternate buffer (no WAR barrier)
#pragma unroll
        for (int r = 0; r < TM; ++r) {
            float i0, i1, f0, f1, g0, g1, o0, o1;
            unpack2(acc[0][r], i0, i1);
            unpack2(acc[1][r], f0, f1);
            unpack2(acc[2][r], g0, g1);
            unpack2(acc[3][r], o0, o1);
            int off = (4 * r + rsub) * HSTR + j0;
            float c0n = sigf(f0) * c0r[r][0] + sigf(i0) * tanh_fast(g0);
            float c1n = sigf(f1) * c0r[r][1] + sigf(i1) * tanh_fast(g1);
            c0r[r][0] = c0n;
            c0r[r][1] = c1n;
            h0n[off]     = sigf(o0) * tanh_fast(c0n);
            h0n[off + 1] = sigf(o1) * tanh_fast(c1n);
        }
        __syncthreads();                              // B1: h0n visible

        // layer1 gates: pre1 + h0n@W_ih1^T + h1c@W_hh1^T
#pragma unroll
        for (int r = 0; r < TM; ++r)
#pragma unroll
            for (int g = 0; g < 4; ++g)
                acc[g][r] = *(const u64*)(sh_pre1 + g * HID + j0);
        gemm128_2(acc, g_Wt1, h0n, rsub, cg);
        gemm128_2(acc, g_Wt1 + HID * GSZ, h1c, rsub, cg);

        // cell 1
#pragma unroll
        for (int r = 0; r < TM; ++r) {
            float i0, i1, f0, f1, g0, g1, o0, o1;
            unpack2(acc[0][r], i0, i1);
            unpack2(acc[1][r], f0, f1);
            unpack2(acc[2][r], g0, g1);
            unpack2(acc[3][r], o0, o1);
            int off = (4 * r + rsub) * HSTR + j0;
            float c0n = sigf(f0) * c1r[r][0] + sigf(i0) * tanh_fast(g0);
            float c1n = sigf(f1) * c1r[r][1] + sigf(i1) * tanh_fast(g1);
            c1r[r][0] = c0n;
            c1r[r][1] = c1n;
            h1n[off]     = sigf(o0) * tanh_fast(c0n);
            h1n[off + 1] = sigf(o1) * tanh_fast(c1n);
        }
        __syncthreads();                              // B2: h1n visible

        // output head: out = h1n @ W_out^T + b_out ; also becomes prev
        for (int idx = tid; idx < M * NVAR; idx += THREADS) {
            int m = idx / NVAR, v = idx - m * NVAR;
            const float* hrow = h1n + m * HSTR;
            const float* wrow = sh_Wout + v * HID;
            float s0 = sh_bout[v], s1 = 0.f, s2 = 0.f, s3 = 0.f;
#pragma unroll 8
            for (int k = 0; k < HID; k += 4) {
                s0 = fmaf(hrow[k],     wrow[k],     s0);
                s1 = fmaf(hrow[k + 1], wrow[k + 1], s1);
                s2 = fmaf(hrow[k + 2], wrow[k + 2], s2);
                s3 = fmaf(hrow[k + 3], wrow[k + 3], s3);
            }
            float s = (s0 + s1) + (s2 + s3);
            sh_prev[m * 12 + v] = s;
            outp[((size_t)(m0 + m) * T + t) * NVAR + v] = s;
        }
        __syncthreads();                              // B3: prev visible

        // swap ping-pong buffers
        float* tmp;
        tmp = h0c; h0c = h0n; h0n = tmp;
        tmp = h1c; h1c = h1n; h1n = tmp;
    }
}

extern "C" void kernel_launch(void* const* d_in, const int* in_sizes, int n_in,
                              void* d_out, int out_size) {
    // input order: z, scenario, [seq_length], emb, W_init, b_init, W_ih0, W_hh0,
    //              b_ih0, b_hh0, W_ih1, W_hh1, b_ih1, b_hh1, W_out, b_out
    int off = (n_in >= 16) ? 1 : 0;   // seq_length scalar present or not
    const float* z      = (const float*)d_in[0];
    const int*   scen   = (const int*)d_in[1];
    const float* emb    = (const float*)d_in[2 + off];
    const float* W_init = (const float*)d_in[3 + off];
    const float* b_init = (const float*)d_in[4 + off];
    const float* W_ih0  = (const float*)d_in[5 + off];
    const float* W_hh0  = (const float*)d_in[6 + off];
    const float* b_ih0  = (const float*)d_in[7 + off];
    const float* b_hh0  = (const float*)d_in[8 + off];
    const float* W_ih1  = (const float*)d_in[9 + off];
    const float* W_hh1  = (const float*)d_in[10 + off];
    const float* b_ih1  = (const float*)d_in[11 + off];
    const float* b_hh1  = (const float*)d_in[12 + off];
    const float* W_out  = (const float*)d_in[13 + off];
    const float* b_out  = (const float*)d_in[14 + off];
    float* outp = (float*)d_out;

    int B = in_sizes[0] / LAT;
    int T = out_size / (B * NVAR);

    cudaFuncSetAttribute(lstm_kernel,
                         cudaFuncAttributeMaxDynamicSharedMemorySize, SMEM_BYTES);

    transpose_kernel<<<(HID * GSZ + 255) / 256, 256>>>(W_hh0, W_ih1, W_hh1);
    lstm_kernel<<<B / M, THREADS, SMEM_BYTES>>>(
        z, scen, emb, W_init, b_init, W_ih0,
        b_ih0, b_hh0, b_ih1, b_hh1, W_out, b_out, outp, T);
}

// round 14
// speedup vs baseline: 5.5584x; 3.8862x over previous
#include <cuda_runtime.h>
#include <cuda_fp16.h>
#include <cstdint>

#define NVAR   9
#define NSCEN  4
#define IH0_W  137
#define INIT_W 160
#define MR     32      // batch rows per CTA
#define THREADS 256

// ---------------- device globals (built by setup_kernel each launch) --------
// B fragment image: [mat 0..3][kt 0..7][np 0..31][lane 0..31][8 halfs]
// mat: 0=W_hh0, 1=Wfold(=Wp*Wout), 2=W_ih1, 3=W_hh1 ; each [N=512, K=128]
__device__ __align__(16) __half g_Bpk[4 * 65536];
__device__ float g_P0[NSCEN * 512];   // se@Wih0_se + b_ih0 + b_hh0
__device__ float g_QI[NSCEN * 512];   // se@Winit_se + b_init
__device__ float g_bf[512];           // Wp @ b_out
__device__ float g_pre1[512];         // b_ih1 + b_hh1

__global__ void setup_kernel(const float* __restrict__ emb,
                             const float* __restrict__ W_init, const float* __restrict__ b_init,
                             const float* __restrict__ W_ih0,  const float* __restrict__ b_ih0,
                             const float* __restrict__ b_hh0,  const float* __restrict__ W_ih1,
                             const float* __restrict__ W_hh1,  const float* __restrict__ b_ih1,
                             const float* __restrict__ b_hh1,  const float* __restrict__ W_hh0,
                             const float* __restrict__ W_out,  const float* __restrict__ b_out) {
    int i = blockIdx.x * blockDim.x + threadIdx.x;
    if (i < 262144) {
        int mat = i >> 16, rem = i & 65535;
        int kt = (rem >> 13) & 7, np = (rem >> 8) & 31, lane = (rem >> 3) & 31, h = rem & 7;
        int n = np * 16 + (h >> 2) * 8 + (lane >> 2);
        int hi = h & 3;
        int k = kt * 16 + ((lane & 3) << 1) + ((hi >> 1) << 3) + (hi & 1);
        float v;
        if (mat == 0)      v = W_hh0[n * 128 + k];
        else if (mat == 1) { v = 0.f;
            for (int q = 0; q < NVAR; ++q) v += W_ih0[n * IH0_W + q] * W_out[q * 128 + k]; }
        else if (mat == 2) v = W_ih1[n * 128 + k];
        else               v = W_hh1[n * 128 + k];
        g_Bpk[i] = __float2half_rn(v);
    } else if (i < 262144 + 2048) {
        int j = i - 262144; int s = j >> 9, col = j & 511;
        float a = b_ih0[col] + b_hh0[col];
        const float* e = emb + s * 128; const float* wr = W_ih0 + col * IH0_W + NVAR;
        for (int k = 0; k < 128; ++k) a += e[k] * wr[k];
        g_P0[j] = a;
    } else if (i < 262144 + 4096) {
        int j = i - 262144 - 2048; int s = j >> 9, col = j & 511;
        float a = b_init[col];
        const float* e = emb + s * 128; const float* wr = W_init + col * INIT_W + 32;
        for (int k = 0; k < 128; ++k) a += e[k] * wr[k];
        g_QI[j] = a;
    } else if (i < 262144 + 4608) {
        int col = i - 262144 - 4096;
        float a = 0.f;
        for (int q = 0; q < NVAR; ++q) a += W_ih0[col * IH0_W + q] * b_out[q];
        g_bf[col] = a;
    } else if (i < 262144 + 5120) {
        int col = i - 262144 - 4608;
        g_pre1[col] = b_ih1[col] + b_hh1[col];
    }
}

// ---------------- SMEM byte offsets ----------------
#define O_H0    0          // 32 x 136 half (row stride 272B)
#define O_H1    8704
#define O_H1F   17408      // 32 x 132 float (stride 528B)
#define O_P0    34304      // 4 x 520 float (padded stride vs banks)
#define O_BF    42624      // 512 float
#define O_PRE1  44672      // 512 float
#define O_WOUT  46720      // 9 x 128 float
#define O_BOUT  51328      // 16 float
#define O_SCEN  51392      // 32 int
#define O_FLAG  51520
#define SMEM_SZ 51584

static __device__ __forceinline__ uint32_t smem_u32(const void* p) {
    uint32_t a;
    asm("{ .reg .u64 t; cvta.to.shared.u64 t, %1; cvt.u32.u64 %0, t; }" : "=r"(a) : "l"(p));
    return a;
}
static __device__ __forceinline__ void ldmat4(uint32_t* r, uint32_t addr) {
    asm volatile("ldmatrix.sync.aligned.m8n8.x4.shared.b16 {%0,%1,%2,%3}, [%4];"
        : "=r"(r[0]), "=r"(r[1]), "=r"(r[2]), "=r"(r[3]) : "r"(addr));
}
static __device__ __forceinline__ void mma16816(float* d, const uint32_t* a,
                                                uint32_t b0, uint32_t b1) {
    asm volatile("mma.sync.aligned.m16n8k16.row.col.f32.f16.f16.f32 "
        "{%0,%1,%2,%3}, {%4,%5,%6,%7}, {%8,%9}, {%0,%1,%2,%3};"
        : "+f"(d[0]), "+f"(d[1]), "+f"(d[2]), "+f"(d[3])
        : "r"(a[0]), "r"(a[1]), "r"(a[2]), "r"(a[3]), "r"(b0), "r"(b1));
}
static __device__ __forceinline__ float sigf(float x) {
    return __fdividef(1.0f, 1.0f + __expf(-x));
}
static __device__ __forceinline__ float tanhf_(float x) {
    return __fdividef(2.0f, 1.0f + __expf(-2.0f * x)) - 1.0f;
}

// one K=128 gemm accumulation: d += A(h tile at hoff) @ B(mat)^T
static __device__ __forceinline__ void do_gemm(float d[2][8][4], const char* smbase,
                                               int hoff, int mat, int w, int lane) {
    uint32_t hb = smem_u32(smbase + hoff);
    const char* bp = (const char*)g_Bpk + (size_t)mat * 131072;
#pragma unroll
    for (int kt = 0; kt < 8; ++kt) {
        uint32_t ad = hb + (lane & 15) * 272 + kt * 32 + ((lane >> 4) << 4);
        uint32_t a0[4], a1[4];
        ldmat4(a0, ad);
        ldmat4(a1, ad + 16 * 272);
#pragma unroll
        for (int p = 0; p < 4; ++p) {
            uint4 b = *(const uint4*)(bp + (size_t)((kt * 32) + p * 8 + w) * 512 + lane * 16);
            mma16816(d[0][2 * p],     a0, b.x, b.y);
            mma16816(d[0][2 * p + 1], a0, b.z, b.w);
            mma16816(d[1][2 * p],     a1, b.x, b.y);
            mma16816(d[1][2 * p + 1], a1, b.z, b.w);
        }
    }
}

__global__ void __launch_bounds__(THREADS, 2)
lstm_mma(const float* __restrict__ z, const int* __restrict__ scen_raw,
         const float* __restrict__ W_init, const float* __restrict__ W_out,
         const float* __restrict__ b_out, float* __restrict__ outp, int T) {
    extern __shared__ char sm[];
    float* shP0   = (float*)(sm + O_P0);
    float* shBF   = (float*)(sm + O_BF);
    float* shPre1 = (float*)(sm + O_PRE1);
    float* shWout = (float*)(sm + O_WOUT);
    float* shBout = (float*)(sm + O_BOUT);
    int*   shScen = (int*)(sm + O_SCEN);
    int*   shFlag = (int*)(sm + O_FLAG);

    const int tid = threadIdx.x;
    const int lane = tid & 31, w = tid >> 5;
    const int m0 = blockIdx.x * MR;

    if (tid == 0) *shFlag = 1;
    __syncthreads();
    {
        const unsigned* su = (const unsigned*)scen_raw;
        for (int k = tid; k < 512; k += THREADS)
            if (su[2 * k + 1] != 0u) *shFlag = 0;
    }
    __syncthreads();
    const int is64 = *shFlag;

    // tables
    for (int i = tid; i < NSCEN * 512; i += THREADS)
        shP0[(i >> 9) * 520 + (i & 511)] = g_P0[i];
    for (int i = tid; i < 512; i += THREADS) { shBF[i] = g_bf[i]; shPre1[i] = g_pre1[i]; }
    for (int i = tid; i < NVAR * 128; i += THREADS) shWout[i] = W_out[i];
    if (tid < NVAR) shBout[tid] = b_out[tid];
    for (int m = tid; m < MR; m += THREADS)
        shScen[m] = is64 ? scen_raw[2 * (m0 + m)] : scen_raw[m0 + m];
    __syncthreads();

    // ---- phase 1: h_init (z @ Winit_z^T + QI[scen]); c in regs, h fp16 ----
    float c0r[16], c1r[16];
#pragma unroll
    for (int rt = 0; rt < 2; ++rt)
#pragma unroll
        for (int e = 0; e < 2; ++e)
#pragma unroll
            for (int j = 0; j < 4; ++j) {
                int row = rt * 16 + (lane >> 2) + ((j >> 1) << 3);
                int u   = (w << 4) + e * 8 + ((lane & 3) << 1) + (j & 1);
                int s = shScen[row];
                float v[4];
#pragma unroll
                for (int slot = 0; slot < 4; ++slot) {
                    int jd = slot * 128 + u;
                    float a = g_QI[s * 512 + jd];
                    const float* zr = z + (size_t)(m0 + row) * 32;
                    const float* wr = W_init + (size_t)jd * INIT_W;
                    for (int k = 0; k < 32; ++k) a += zr[k] * wr[k];
                    v[slot] = a;
                }
                int ci = rt * 8 + e * 4 + j;
                *(__half*)(sm + O_H0 + row * 272 + u * 2) = __float2half_rn(v[0]);
                c0r[ci] = v[1];
                *(__half*)(sm + O_H1 + row * 272 + u * 2) = __float2half_rn(v[2]);
                c1r[ci] = v[3];
            }
    __syncthreads();

    // ---- time loop ----
    for (int t = 0; t < T; ++t) {
        float d[2][8][4];
#pragma unroll
        for (int a = 0; a < 2; ++a)
#pragma unroll
            for (int b = 0; b < 8; ++b)
#pragma unroll
                for (int c = 0; c < 4; ++c) d[a][b][c] = 0.f;

        do_gemm(d, sm, O_H0, 0, w, lane);           // h0 @ Whh0^T
        if (t) do_gemm(d, sm, O_H1, 1, w, lane);    // h1 @ Wfold^T (prev folded)
        __syncthreads();                            // B1: all reads of h0 done

        float bs = (t > 0) ? 1.f : 0.f;
#pragma unroll
        for (int rt = 0; rt < 2; ++rt)
#pragma unroll
            for (int e = 0; e < 2; ++e) {
                float hv[4];
#pragma unroll
                for (int j = 0; j < 4; ++j) {
                    int row = rt * 16 + (lane >> 2) + ((j >> 1) << 3);
                    int u   = (w << 4) + e * 8 + ((lane & 3) << 1) + (j & 1);
                    int s = shScen[row];
                    const float* p0 = shP0 + s * 520;
                    float ip = d[rt][0 + e][j] + p0[u]       + bs * shBF[u];
                    float fp = d[rt][2 + e][j] + p0[128 + u] + bs * shBF[128 + u];
                    float gp = d[rt][4 + e][j] + p0[256 + u] + bs * shBF[256 + u];
                    float op = d[rt][6 + e][j] + p0[384 + u] + bs * shBF[384 + u];
                    int ci = rt * 8 + e * 4 + j;
                    float cn = sigf(fp) * c0r[ci] + sigf(ip) * tanhf_(gp);
                    c0r[ci] = cn;
                    hv[j] = sigf(op) * tanhf_(cn);
                }
                int row0 = rt * 16 + (lane >> 2);
                int ub = (w << 4) + e * 8 + ((lane & 3) << 1);
                *(__half2*)(sm + O_H0 + row0 * 272 + ub * 2)       = __floats2half2_rn(hv[0], hv[1]);
                *(__half2*)(sm + O_H0 + (row0 + 8) * 272 + ub * 2) = __floats2half2_rn(hv[2], hv[3]);
            }
        __syncthreads();                            // B2: h0n visible

#pragma unroll
        for (int a = 0; a < 2; ++a)
#pragma unroll
            for (int b = 0; b < 8; ++b)
#pragma unroll
                for (int c = 0; c < 4; ++c) d[a][b][c] = 0.f;
        do_gemm(d, sm, O_H0, 2, w, lane);           // h0n @ Wih1^T
        do_gemm(d, sm, O_H1, 3, w, lane);           // h1  @ Whh1^T
        __syncthreads();                            // B3: all reads of h1 done

#pragma unroll
        for (int rt = 0; rt < 2; ++rt)
#pragma unroll
            for (int e = 0; e < 2; ++e) {
                float hv[4];
#pragma unroll
                for (int j = 0; j < 4; ++j) {
                    int u = (w << 4) + e * 8 + ((lane & 3) << 1) + (j & 1);
                    float ip = d[rt][0 + e][j] + shPre1[u];
                    float fp = d[rt][2 + e][j] + shPre1[128 + u];
                    float gp = d[rt][4 + e][j] + shPre1[256 + u];
                    float op = d[rt][6 + e][j] + shPre1[384 + u];
                    int ci = rt * 8 + e * 4 + j;
                    float cn = sigf(fp) * c1r[ci] + sigf(ip) * tanhf_(gp);
                    c1r[ci] = cn;
                    hv[j] = sigf(op) * tanhf_(cn);
                }
                int row0 = rt * 16 + (lane >> 2);
                int ub = (w << 4) + e * 8 + ((lane & 3) << 1);
                *(__half2*)(sm + O_H1 + row0 * 272 + ub * 2)       = __floats2half2_rn(hv[0], hv[1]);
                *(__half2*)(sm + O_H1 + (row0 + 8) * 272 + ub * 2) = __floats2half2_rn(hv[2], hv[3]);
                *(float2*)(sm + O_H1F + row0 * 528 + ub * 4)       = make_float2(hv[0], hv[1]);
                *(float2*)(sm + O_H1F + (row0 + 8) * 528 + ub * 4) = make_float2(hv[2], hv[3]);
            }
        __syncthreads();                            // B4: h1n (fp16+fp32) visible

        // output head from fp32 h1n
        for (int idx = tid; idx < MR * NVAR; idx += THREADS) {
            int m = idx / NVAR, v = idx - m * NVAR;
            const float* hr = (const float*)(sm + O_H1F) + m * 132;
            const float* wr = shWout + v * 128;
            float s0 = shBout[v], s1 = 0.f, s2 = 0.f, s3 = 0.f;
#pragma unroll 8
            for (int k = 0; k < 128; k += 4) {
                s0 = fmaf(hr[k],     wr[k],     s0);
                s1 = fmaf(hr[k + 1], wr[k + 1], s1);
                s2 = fmaf(hr[k + 2], wr[k + 2], s2);
                s3 = fmaf(hr[k + 3], wr[k + 3], s3);
            }
            outp[((size_t)(m0 + m) * T + t) * NVAR + v] = (s0 + s1) + (s2 + s3);
        }
        // next-step G0 reads h0/h1 (stable until next B1/B3); no extra barrier needed
    }
}

extern "C" void kernel_launch(void* const* d_in, const int* in_sizes, int n_in,
                              void* d_out, int out_size) {
    int off = (n_in >= 16) ? 1 : 0;
    const float* z      = (const float*)d_in[0];
    const int*   scen   = (const int*)d_in[1];
    const float* emb    = (const float*)d_in[2 + off];
    const float* W_init = (const float*)d_in[3 + off];
    const float* b_init = (const float*)d_in[4 + off];
    const float* W_ih0  = (const float*)d_in[5 + off];
    const float* W_hh0  = (const float*)d_in[6 + off];
    const float* b_ih0  = (const float*)d_in[7 + off];
    const float* b_hh0  = (const float*)d_in[8 + off];
    const float* W_ih1  = (const float*)d_in[9 + off];
    const float* W_hh1  = (const float*)d_in[10 + off];
    const float* b_ih1  = (const float*)d_in[11 + off];
    const float* b_hh1  = (const float*)d_in[12 + off];
    const float* W_out  = (const float*)d_in[13 + off];
    const float* b_out  = (const float*)d_in[14 + off];
    float* outp = (float*)d_out;

    int B = in_sizes[0] / 32;
    int T = out_size / (B * NVAR);

    int setup_n = 262144 + 5120;
    setup_kernel<<<(setup_n + 255) / 256, 256>>>(emb, W_init, b_init, W_ih0, b_ih0,
                                                 b_hh0, W_ih1, W_hh1, b_ih1, b_hh1,
                                                 W_hh0, W_out, b_out);
    cudaFuncSetAttribute(lstm_mma, cudaFuncAttributeMaxDynamicSharedMemorySize, SMEM_SZ);
    lstm_mma<<<B / MR, THREADS, SMEM_SZ>>>(z, scen, W_init, W_out, b_out, outp, T);
}